// round 15
// baseline (speedup 1.0000x reference)
#include <cuda_runtime.h>
#include <math.h>

#define BB 64
#define LL 4096
#define N0 1023
#define K1 512
#define N1 513
#define T1 (BB*N1)
#define EMB 256

// ------------------------- device scratch (no allocs) ----------------------
static __device__ float g_h[BB*N0*EMB];
static __device__ float g_xn[BB*N0*EMB];
static __device__ float g_xn2[BB*N0*EMB];
static __device__ float g_scores[BB*1024];
static __device__ float g_escore[T1];
static __device__ float g_xbT[BB*32*1024];
static __device__ float g_act[BB*N0*128];
static __device__ float g_mid[T1*EMB];
static __device__ float g_out2[T1*EMB];
static __device__ float g_probs[T1*4];
static __device__ float g_topV[T1];
static __device__ int   g_selidx[BB*K1];
static __device__ unsigned char g_mask[BB*1024];
static __device__ int   g_elist[4*T1];
static __device__ int   g_ecnt[4];
static __device__ float g_imp[4];
static __device__ float g_embwT[128*EMB];
static __device__ float g_w1T[8*EMB];

__device__ __forceinline__ float geluf(float x){
    return 0.5f*x*(1.0f + erff(x*0.70710678118654752440f));
}
__device__ __forceinline__ float wsum(float v){
    #pragma unroll
    for (int o = 16; o > 0; o >>= 1) v += __shfl_down_sync(0xffffffffu, v, o);
    return v;
}

// ------------------- weight pre-transpose (coalesced reads later) ----------
__global__ void k_prep(const float* __restrict__ embw, const float* __restrict__ w1){
    int r = blockIdx.x, d = threadIdx.x;
    if (r < 128) g_embwT[r*EMB + d] = embw[d*128 + r];
    else         g_w1T[(r-128)*EMB + d] = w1[d*8 + (r-128)];
}

// ------------------- embedding conv as im2col GEMM + pos -------------------
__global__ void k_embed(const float* __restrict__ x, const float* __restrict__ eb,
                        const float* __restrict__ pos){
    int b = blockIdx.y, tile0 = blockIdx.x*16, tid = threadIdx.x, d = tid;
    __shared__ __align__(16) float X[16][128];
    for (int i = tid; i < 16*128; i += 256){
        int tt = i >> 7, ck = i & 127, c = ck >> 3, k = ck & 7;
        int n = tile0 + tt;
        X[tt][ck] = (n < N0) ? x[((size_t)b*16 + c)*LL + 4*n + k] : 0.f;
    }
    __syncthreads();
    float acc[16];
    #pragma unroll
    for (int t = 0; t < 16; t++) acc[t] = 0.f;
    for (int k4 = 0; k4 < 32; k4++){
        float w0 = g_embwT[(k4*4+0)*EMB + d];
        float w1v = g_embwT[(k4*4+1)*EMB + d];
        float w2v = g_embwT[(k4*4+2)*EMB + d];
        float w3v = g_embwT[(k4*4+3)*EMB + d];
        #pragma unroll
        for (int tt = 0; tt < 16; tt++){
            float4 xv = *(const float4*)&X[tt][k4*4];
            acc[tt] += xv.x*w0 + xv.y*w1v + xv.z*w2v + xv.w*w3v;
        }
    }
    float bv = eb[d];
    #pragma unroll
    for (int tt = 0; tt < 16; tt++){
        int n = tile0 + tt;
        if (n < N0) g_h[((size_t)b*N0 + n)*EMB + d] = acc[tt] + bv + pos[(size_t)n*EMB + d];
    }
}

// ---------------- rmsnorm + attn-score MLP (+ optional h = xn*score) -------
template<bool SCALE>
__global__ void k_norm_attn(const float* __restrict__ ng, const float* __restrict__ b1,
                            const float* __restrict__ w2, const float* __restrict__ b2,
                            int N){
    int t = blockIdx.x, d = threadIdx.x;
    __shared__ float sxn[EMB];
    __shared__ float red[8], hid[8], sbc[2];
    float v = g_h[(size_t)t*EMB + d];
    float sq = wsum(v*v);
    int w = d >> 5, l = d & 31;
    if (l == 0) red[w] = sq;
    __syncthreads();
    if (d == 0){
        float s = 0.f;
        #pragma unroll
        for (int i = 0; i < 8; i++) s += red[i];
        sbc[0] = 16.0f / fmaxf(sqrtf(s), 1e-12f);
    }
    __syncthreads();
    float xnv = v * sbc[0] * ng[d];
    sxn[d] = xnv;
    g_xn[(size_t)t*EMB + d] = xnv;
    __syncthreads();
    {
        float s = 0.f;
        #pragma unroll
        for (int q = 0; q < 8; q++){ int dd = l + 32*q; s += sxn[dd]*g_w1T[w*EMB + dd]; }
        s = wsum(s);
        if (l == 0) hid[w] = tanhf(s + b1[w]);
    }
    __syncthreads();
    if (d == 0){
        float s = 0.f;
        #pragma unroll
        for (int j = 0; j < 8; j++) s += hid[j]*w2[j];
        s += b2[0];
        float sc = 1.0f/(1.0f + expf(-s));
        int b = t / N, n = t - b*N;
        g_scores[b*1024 + n] = sc;
        sbc[1] = sc;
    }
    __syncthreads();
    if (SCALE) g_h[(size_t)t*EMB + d] = sxn[d]*sbc[1];
}

// attn on raw (un-normed) h -> end_scores
__global__ void k_attn_raw(const float* __restrict__ b1, const float* __restrict__ w2,
                           const float* __restrict__ b2){
    int t = blockIdx.x, d = threadIdx.x;
    __shared__ float sx[EMB];
    __shared__ float hid[8];
    sx[d] = g_h[(size_t)t*EMB + d];
    __syncthreads();
    int w = d >> 5, l = d & 31;
    float s = 0.f;
    #pragma unroll
    for (int q = 0; q < 8; q++){ int dd = l + 32*q; s += sx[dd]*g_w1T[w*EMB + dd]; }
    s = wsum(s);
    if (l == 0) hid[w] = tanhf(s + b1[w]);
    __syncthreads();
    if (d == 0){
        float s2 = 0.f;
        #pragma unroll
        for (int j = 0; j < 8; j++) s2 += hid[j]*w2[j];
        s2 += b2[0];
        g_escore[t] = 1.0f/(1.0f + expf(-s2));
    }
}

// ---------------- rmsnorm g_h -> g_xn2 -------------------------------------
__global__ void k_rmsnorm(const float* __restrict__ ng){
    int t = blockIdx.x, d = threadIdx.x;
    __shared__ float red[8];
    __shared__ float sinv;
    float v = g_h[(size_t)t*EMB + d];
    float sq = wsum(v*v);
    if ((d & 31) == 0) red[d >> 5] = sq;
    __syncthreads();
    if (d == 0){
        float s = 0.f;
        #pragma unroll
        for (int i = 0; i < 8; i++) s += red[i];
        sinv = 16.0f / fmaxf(sqrtf(s), 1e-12f);
    }
    __syncthreads();
    g_xn2[(size_t)t*EMB + d] = v * sinv * ng[d];
}

__global__ void k_gelu(int n){
    int i = blockIdx.x*blockDim.x + threadIdx.x, st = gridDim.x*blockDim.x;
    for (; i < n; i += st) g_h[i] = geluf(g_h[i]);
}

// ---------------- per-batch top-512 (bitonic 1024) + mask ------------------
__global__ void k_topk(){
    int b = blockIdx.x, tid = threadIdx.x;   // 512 threads
    __shared__ float v[1024];
    __shared__ int   ix[1024];
    __shared__ int   sel[K1];
    for (int i = tid; i < 1024; i += 512){
        v[i] = (i < N0) ? g_scores[b*1024 + i] : -1e30f;
        ix[i] = i;
    }
    __syncthreads();
    for (int k = 2; k <= 1024; k <<= 1){
        for (int j = k >> 1; j > 0; j >>= 1){
            for (int i = tid; i < 1024; i += 512){
                int p = i ^ j;
                if (p > i){
                    bool up = ((i & k) == 0);
                    if ((v[i] > v[p]) == up){
                        float tv = v[i]; v[i] = v[p]; v[p] = tv;
                        int ti = ix[i]; ix[i] = ix[p]; ix[p] = ti;
                    }
                }
            }
            __syncthreads();
        }
    }
    sel[tid] = ix[512 + tid];           // top-512 (largest) indices
    __syncthreads();
    for (int k = 2; k <= K1; k <<= 1){  // sort indices ascending
        for (int j = k >> 1; j > 0; j >>= 1){
            int i = tid, p = i ^ j;
            if (p > i){
                bool up = ((i & k) == 0);
                if ((sel[i] > sel[p]) == up){ int tt = sel[i]; sel[i] = sel[p]; sel[p] = tt; }
            }
            __syncthreads();
        }
    }
    g_selidx[b*K1 + tid] = sel[tid];
    for (int i = tid; i < 1024; i += 512) g_mask[b*1024 + i] = 0;
    __syncthreads();
    g_mask[b*1024 + sel[tid]] = 1;
}

__global__ void k_gather(){
    int j = blockIdx.x, b = blockIdx.y, d = threadIdx.x;
    int n = g_selidx[b*K1 + j];
    float s = g_scores[b*1024 + n];
    g_h[((size_t)b*N1 + j)*EMB + d] = g_xn[((size_t)b*N0 + n)*EMB + d]*s;
}

__global__ void k_extra(){
    int b = blockIdx.x, d = threadIdx.x;
    float acc = 0.f;
    const float* xb2 = g_xn + (size_t)b*N0*EMB;
    for (int n = 0; n < N0; n++)
        if (!g_mask[b*1024 + n]) acc += xb2[(size_t)n*EMB + d]*g_scores[b*1024 + n];
    g_h[((size_t)b*N1 + K1)*EMB + d] = acc;
}

// ---------------- MoE gate: softmax + argmax route --------------------------
__global__ void k_zero(){ if (threadIdx.x < 4) g_ecnt[threadIdx.x] = 0; }

__global__ void k_gate(const float* __restrict__ gw, const float* __restrict__ gb){
    int tid = threadIdx.x, warp = tid >> 5, lane = tid & 31;
    int t = blockIdx.x*8 + warp;
    if (t >= T1) return;
    float s0 = 0.f, s1 = 0.f, s2 = 0.f, s3 = 0.f;
    const float4* gw4 = (const float4*)gw;
    #pragma unroll
    for (int q = 0; q < 8; q++){
        int dd = lane + 32*q;
        float xv = g_xn2[(size_t)t*EMB + dd];
        float4 g4 = gw4[dd];
        s0 += xv*g4.x; s1 += xv*g4.y; s2 += xv*g4.z; s3 += xv*g4.w;
    }
    s0 = wsum(s0); s1 = wsum(s1); s2 = wsum(s2); s3 = wsum(s3);
    if (lane == 0){
        float lg[4] = {s0+gb[0], s1+gb[1], s2+gb[2], s3+gb[3]};
        float mx = lg[0];
        #pragma unroll
        for (int e = 1; e < 4; e++) mx = fmaxf(mx, lg[e]);
        float ex[4], sum = 0.f;
        #pragma unroll
        for (int e = 0; e < 4; e++){ ex[e] = expf(lg[e]-mx); sum += ex[e]; }
        float inv = 1.0f/sum;
        int be = 0; float bp = ex[0];
        #pragma unroll
        for (int e = 1; e < 4; e++) if (ex[e] > bp){ bp = ex[e]; be = e; }
        #pragma unroll
        for (int e = 0; e < 4; e++) g_probs[(size_t)t*4 + e] = ex[e]*inv;
        g_topV[t] = bp*inv;
        int pos = atomicAdd(&g_ecnt[be], 1);   // list order irrelevant to values
        g_elist[be*T1 + pos] = t;
    }
}

__global__ void k_imp(){
    int e = blockIdx.x, tid = threadIdx.x;
    __shared__ float red[8];
    float acc = 0.f;
    for (int t = tid; t < T1; t += 256) acc += g_probs[(size_t)t*4 + e];
    acc = wsum(acc);
    if ((tid & 31) == 0) red[tid >> 5] = acc;
    __syncthreads();
    if (tid == 0){
        float s = 0.f;
        #pragma unroll
        for (int i = 0; i < 8; i++) s += red[i];
        g_imp[e] = s;
    }
}

// ---------------- routed expert GEMM (16 tokens x 256 out, K=256) ----------
template<bool FIRST>
__global__ void k_expert(const float* __restrict__ W, const float* __restrict__ bias){
    int e = blockIdx.y;
    int cnt = g_ecnt[e];
    int base = blockIdx.x*16;
    if (base >= cnt) return;
    int m = min(16, cnt - base);
    __shared__ __align__(16) float X[16][EMB];
    __shared__ int tl[16];
    int d = threadIdx.x;
    if (d < 16) tl[d] = (base + d < cnt) ? g_elist[e*T1 + base + d] : 0;
    __syncthreads();
    const float* src = FIRST ? g_xn2 : g_mid;
    for (int tt = 0; tt < 16; tt++)
        X[tt][d] = (tt < m) ? src[(size_t)tl[tt]*EMB + d] : 0.f;
    __syncthreads();
    float acc[16];
    #pragma unroll
    for (int i = 0; i < 16; i++) acc[i] = 0.f;
    const float* Wd = W + (size_t)e*EMB*EMB + d;
    for (int k4 = 0; k4 < EMB/4; k4++){
        float w0 = Wd[(size_t)(k4*4+0)*EMB];
        float w1v = Wd[(size_t)(k4*4+1)*EMB];
        float w2v = Wd[(size_t)(k4*4+2)*EMB];
        float w3v = Wd[(size_t)(k4*4+3)*EMB];
        #pragma unroll
        for (int tt = 0; tt < 16; tt++){
            float4 xv = *(const float4*)&X[tt][k4*4];
            acc[tt] += xv.x*w0 + xv.y*w1v + xv.z*w2v + xv.w*w3v;
        }
    }
    float bv = bias[e*EMB + d];
    float* dst = FIRST ? g_mid : g_out2;
    for (int tt = 0; tt < m; tt++){
        float v = acc[tt] + bv;
        if (FIRST) v = geluf(v);
        dst[(size_t)tl[tt]*EMB + d] = v;
    }
}

// ---------------- MoE combine: h += gelu(rmsnorm(xn2 + out*topV)) ----------
__global__ void k_moe_combine(const float* __restrict__ gamma){
    int t = blockIdx.x, d = threadIdx.x;
    __shared__ float red[8];
    __shared__ float sinv;
    float v = g_xn2[(size_t)t*EMB + d] + g_out2[(size_t)t*EMB + d]*g_topV[t];
    float sq = wsum(v*v);
    if ((d & 31) == 0) red[d >> 5] = sq;
    __syncthreads();
    if (d == 0){
        float s = 0.f;
        #pragma unroll
        for (int i = 0; i < 8; i++) s += red[i];
        sinv = 16.0f / fmaxf(sqrtf(s), 1e-12f);
    }
    __syncthreads();
    g_h[(size_t)t*EMB + d] += geluf(v * sinv * gamma[d]);
}

// ---------------- inception: bottleneck 1x1 + maxpool->1x1 -----------------
__global__ void k_bott(const float* __restrict__ bw, const float* __restrict__ mw,
                       const float* __restrict__ bng, const float* __restrict__ bnb,
                       int N){
    int b = blockIdx.y, tile0 = blockIdx.x*32, tid = threadIdx.x;
    __shared__ float sm[34][EMB];
    __shared__ float wbs[32][33], wms[32][33];
    for (int i = tid; i < 34*EMB; i += 256){
        int p = i >> 8, d = i & 255;
        int n = tile0 + p - 1;
        sm[p][d] = (n >= 0 && n < N) ? g_xn2[((size_t)b*N + n)*EMB + d] : -1e30f;
    }
    int f = tid & 31, grp = tid >> 5, p1 = grp*4 + 1;
    float ab[4] = {0,0,0,0}, am[4] = {0,0,0,0};
    for (int ch = 0; ch < 8; ch++){
        __syncthreads();
        for (int i = tid; i < 1024; i += 256){
            int ff = i >> 5, dd = i & 31;
            wbs[ff][dd] = bw[ff*EMB + ch*32 + dd];
            wms[ff][dd] = mw[ff*EMB + ch*32 + dd];
        }
        __syncthreads();
        #pragma unroll 4
        for (int dd = 0; dd < 32; dd++){
            int d = ch*32 + dd;
            float w_b = wbs[f][dd], w_m = wms[f][dd];
            float s0 = sm[p1-1][d], s1 = sm[p1][d], s2 = sm[p1+1][d];
            float s3 = sm[p1+2][d], s4 = sm[p1+3][d], s5 = sm[p1+4][d];
            ab[0] += s1*w_b; ab[1] += s2*w_b; ab[2] += s3*w_b; ab[3] += s4*w_b;
            am[0] += fmaxf(fmaxf(s0,s1),s2)*w_m;
            am[1] += fmaxf(fmaxf(s1,s2),s3)*w_m;
            am[2] += fmaxf(fmaxf(s2,s3),s4)*w_m;
            am[3] += fmaxf(fmaxf(s3,s4),s5)*w_m;
        }
    }
    float bsc = rsqrtf(1.0f + 1e-5f);
    float sc = bng[96+f]*bsc, bi = bnb[96+f];
    #pragma unroll
    for (int tt = 0; tt < 4; tt++){
        int n = tile0 + grp*4 + tt;
        if (n < N){
            g_xbT[((size_t)b*32 + f)*1024 + n] = ab[tt];
            g_act[((size_t)b*N + n)*128 + 96 + f] = geluf(am[tt]*sc + bi);
        }
    }
}

// ---------------- inception: k39/k19/k9 convs + BN + gelu ------------------
__global__ void k_convs(const float* __restrict__ w39, const float* __restrict__ w19,
                        const float* __restrict__ w9, const float* __restrict__ bng,
                        const float* __restrict__ bnb, int N){
    int b = blockIdx.y, tile0 = blockIdx.x*32, tid = threadIdx.x;
    __shared__ float sm[32][70];
    __shared__ float ws[32][69];
    for (int i = tid; i < 32*70; i += 256){
        int g = i/70, p = i - g*70;
        int n = tile0 + p - 19;
        sm[g][p] = (n >= 0 && n < N) ? g_xbT[((size_t)b*32 + g)*1024 + n] : 0.f;
    }
    int f = tid & 31, grp = tid >> 5, pos0 = grp*4;
    float a39[4] = {0,0,0,0}, a19[4] = {0,0,0,0}, a9[4] = {0,0,0,0};
    for (int g = 0; g < 32; g++){
        __syncthreads();
        for (int i = tid; i < 32*67; i += 256){
            int ff = i/67, j = i - ff*67;
            float wv = (j < 39) ? w39[ff*1248 + g*39 + j]
                     : (j < 58) ? w19[ff*608 + g*19 + (j-39)]
                                : w9[ff*288 + g*9 + (j-58)];
            ws[ff][j] = wv;
        }
        __syncthreads();
        {
            float x0 = sm[g][pos0], x1 = sm[g][pos0+1], x2 = sm[g][pos0+2];
            #pragma unroll
            for (int k = 0; k < 39; k++){
                float x3 = sm[g][pos0+3+k];
                float w = ws[f][k];
                a39[0] += x0*w; a39[1] += x1*w; a39[2] += x2*w; a39[3] += x3*w;
                x0 = x1; x1 = x2; x2 = x3;
            }
        }
        {
            float x0 = sm[g][pos0+10], x1 = sm[g][pos0+11], x2 = sm[g][pos0+12];
            #pragma unroll
            for (int k = 0; k < 19; k++){
                float x3 = sm[g][pos0+13+k];
                float w = ws[f][39+k];
                a19[0] += x0*w; a19[1] += x1*w; a19[2] += x2*w; a19[3] += x3*w;
                x0 = x1; x1 = x2; x2 = x3;
            }
        }
        {
            float x0 = sm[g][pos0+15], x1 = sm[g][pos0+16], x2 = sm[g][pos0+17];
            #pragma unroll
            for (int k = 0; k < 9; k++){
                float x3 = sm[g][pos0+18+k];
                float w = ws[f][58+k];
                a9[0] += x0*w; a9[1] += x1*w; a9[2] += x2*w; a9[3] += x3*w;
                x0 = x1; x1 = x2; x2 = x3;
            }
        }
    }
    float bsc = rsqrtf(1.0f + 1e-5f);
    float sc0 = bng[f]*bsc,    bi0 = bnb[f];
    float sc1 = bng[32+f]*bsc, bi1 = bnb[32+f];
    float sc2 = bng[64+f]*bsc, bi2 = bnb[64+f];
    #pragma unroll
    for (int tt = 0; tt < 4; tt++){
        int n = tile0 + pos0 + tt;
        if (n < N){
            size_t base = ((size_t)b*N + n)*128;
            g_act[base + f]      = geluf(a39[tt]*sc0 + bi0);
            g_act[base + 32 + f] = geluf(a19[tt]*sc1 + bi1);
            g_act[base + 64 + f] = geluf(a9[tt]*sc2 + bi2);
        }
    }
}

// ---------------- projection: h += act(T,128) @ proj_w(128,256) + b --------
__global__ void k_proj(const float* __restrict__ W, const float* __restrict__ bias, int T){
    int base = blockIdx.x*16, tid = threadIdx.x, d = tid;
    __shared__ __align__(16) float X[16][128];
    for (int i = tid; i < 16*128; i += 256){
        int tt = i >> 7, kk = i & 127;
        int t = base + tt;
        X[tt][kk] = (t < T) ? g_act[(size_t)t*128 + kk] : 0.f;
    }
    __syncthreads();
    float acc[16];
    #pragma unroll
    for (int i = 0; i < 16; i++) acc[i] = 0.f;
    for (int k4 = 0; k4 < 32; k4++){
        float w0 = W[(k4*4+0)*EMB + d];
        float w1v = W[(k4*4+1)*EMB + d];
        float w2v = W[(k4*4+2)*EMB + d];
        float w3v = W[(k4*4+3)*EMB + d];
        #pragma unroll
        for (int tt = 0; tt < 16; tt++){
            float4 xv = *(const float4*)&X[tt][k4*4];
            acc[tt] += xv.x*w0 + xv.y*w1v + xv.z*w2v + xv.w*w3v;
        }
    }
    float bv = bias[d];
    for (int tt = 0; tt < 16; tt++){
        int t = base + tt;
        if (t < T) g_h[(size_t)t*EMB + d] += acc[tt] + bv;
    }
}

// ---------------- final: logits = gelu(h)@head_w+b, cls + loss -------------
__global__ void k_final(const float* __restrict__ hw, const float* __restrict__ hb,
                        float* __restrict__ out, int out_size){
    int b = blockIdx.x, tid = threadIdx.x, w = tid >> 5, l = tid & 31;
    __shared__ float s_hw[EMB];
    __shared__ float wacc[8];
    s_hw[tid] = hw[tid];
    __syncthreads();
    float local = 0.f;
    float hbias = hb[0];
    for (int j = w; j < N1; j += 8){
        size_t t = (size_t)b*N1 + j;
        float s = 0.f;
        #pragma unroll
        for (int q = 0; q < 8; q++){
            int d = l + 32*q;
            s += geluf(g_h[t*EMB + d])*s_hw[d];
        }
        s = wsum(s);
        if (l == 0) local += (s + hbias)*g_escore[t];
    }
    if (l == 0) wacc[w] = local;
    __syncthreads();
    if (tid == 0){
        float tot = 0.f;
        #pragma unroll
        for (int i = 0; i < 8; i++) tot += wacc[i];
        out[b] = tot/(float)N1;
        if (b == 0 && out_size > BB){
            float m = (g_imp[0]+g_imp[1]+g_imp[2]+g_imp[3])*0.25f;
            float v = 0.f;
            #pragma unroll
            for (int e = 0; e < 4; e++){ float dv = g_imp[e]-m; v += dv*dv; }
            v *= (1.0f/3.0f);
            out[BB] = v/(m*m + 1e-10f);
        }
    }
}

// ---------------------------------------------------------------------------
extern "C" void kernel_launch(void* const* d_in, const int* in_sizes, int n_in,
                              void* d_out, int out_size){
    const float* x       = (const float*)d_in[0];
    const float* emb_w   = (const float*)d_in[3];
    const float* emb_b   = (const float*)d_in[4];
    const float* pos     = (const float*)d_in[5];
    const float* aw1     = (const float*)d_in[6];
    const float* ab1     = (const float*)d_in[7];
    const float* aw2     = (const float*)d_in[8];
    const float* ab2     = (const float*)d_in[9];
    const float* gw      = (const float*)d_in[10];
    const float* gb      = (const float*)d_in[11];
    const float* ew1     = (const float*)d_in[12];
    const float* eb1     = (const float*)d_in[13];
    const float* ew2     = (const float*)d_in[14];
    const float* eb2     = (const float*)d_in[15];
    const float* mgam    = (const float*)d_in[16];
    const float* n1g     = (const float*)d_in[17];
    const float* n2g     = (const float*)d_in[18];
    const float* bott    = (const float*)d_in[19];
    const float* w39     = (const float*)d_in[20];
    const float* w19     = (const float*)d_in[21];
    const float* w9      = (const float*)d_in[22];
    const float* mpw     = (const float*)d_in[23];
    const float* bng     = (const float*)d_in[24];
    const float* bnb     = (const float*)d_in[25];
    const float* pw      = (const float*)d_in[26];
    const float* pb      = (const float*)d_in[27];
    const float* hw      = (const float*)d_in[28];
    const float* hb      = (const float*)d_in[29];
    float* out = (float*)d_out;

    k_prep<<<136, 256>>>(emb_w, aw1);
    k_embed<<<dim3(64, BB), 256>>>(x, emb_b, pos);

    // ---- layer 0 (dense): h = xn*score; h += incep(rmsnorm(h)); h = gelu(h)
    k_norm_attn<true><<<BB*N0, 256>>>(n1g, ab1, aw2, ab2, N0);
    k_rmsnorm<<<BB*N0, 256>>>(n2g);
    k_bott<<<dim3(32, BB), 256>>>(bott, mpw, bng, bnb, N0);
    k_convs<<<dim3(32, BB), 256>>>(w39, w19, w9, bng, bnb, N0);
    k_proj<<<(BB*N0 + 15)/16, 256>>>(pw, pb, BB*N0);
    k_gelu<<<2048, 256>>>(BB*N0*EMB);

    // ---- layer 1 (sparse, ratio 0.5)
    k_norm_attn<false><<<BB*N0, 256>>>(n1g + EMB, ab1, aw2, ab2, N0);
    k_topk<<<BB, 512>>>();
    k_gather<<<dim3(K1, BB), 256>>>();
    k_extra<<<BB, 256>>>();
    k_rmsnorm<<<T1, 256>>>(n2g + EMB);
    // MoE
    k_zero<<<1, 32>>>();
    k_gate<<<(T1 + 7)/8, 256>>>(gw, gb);
    k_imp<<<4, 256>>>();
    k_expert<true><<<dim3((T1 + 15)/16, 4), 256>>>(ew1, eb1);
    k_expert<false><<<dim3((T1 + 15)/16, 4), 256>>>(ew2, eb2);
    k_moe_combine<<<T1, 256>>>(mgam);
    // Inception branch (layer-1 weights)
    k_bott<<<dim3((N1 + 31)/32, BB), 256>>>(bott + 32*EMB, mpw + 32*EMB,
                                            bng + 128, bnb + 128, N1);
    k_convs<<<dim3((N1 + 31)/32, BB), 256>>>(w39 + 32*32*39, w19 + 32*32*19,
                                             w9 + 32*32*9, bng + 128, bnb + 128, N1);
    k_proj<<<(T1 + 15)/16, 256>>>(pw + 128*EMB, pb + EMB, T1);
    // end_scores on pre-gelu h, then fused gelu+head+mean in k_final
    k_attn_raw<<<T1, 256>>>(ab1, aw2, ab2);
    k_final<<<BB, 256>>>(hw, hb, out, out_size);
}

// round 16
// speedup vs baseline: 1.1852x; 1.1852x over previous
#include <cuda_runtime.h>
#include <math.h>

#define BB 64
#define LL 4096
#define N0 1023
#define K1 512
#define N1 513
#define T1 (BB*N1)
#define EMB 256

// ------------------------- device scratch (no allocs) ----------------------
static __device__ float g_h[BB*N0*EMB];
static __device__ float g_xn[BB*N0*EMB];
static __device__ float g_xn2[BB*N0*EMB];
static __device__ float g_scores[BB*1024];
static __device__ float g_escore[T1];
static __device__ float g_xbT[BB*32*1024];
static __device__ float g_act[BB*N0*128];
static __device__ float g_out2[T1*EMB];
static __device__ float g_probs[T1*4];
static __device__ float g_topV[T1];
static __device__ int   g_selidx[BB*K1];
static __device__ unsigned char g_mask[BB*1024];
static __device__ int   g_elist[4*T1];
static __device__ int   g_ecnt[4];
static __device__ float g_imp[4];
static __device__ float g_embwT[128*EMB];
static __device__ float g_w1T[8*EMB];
static __device__ float g_part[BB*8];

__device__ __forceinline__ float geluf(float x){
    return 0.5f*x*(1.0f + erff(x*0.70710678118654752440f));
}
__device__ __forceinline__ float wsum(float v){
    #pragma unroll
    for (int o = 16; o > 0; o >>= 1) v += __shfl_down_sync(0xffffffffu, v, o);
    return v;
}
__device__ __forceinline__ float wsum_all(float v){
    #pragma unroll
    for (int o = 16; o > 0; o >>= 1) v += __shfl_xor_sync(0xffffffffu, v, o);
    return v;
}

// ------------------- weight pre-transpose ----------------------------------
__global__ void k_prep(const float* __restrict__ embw, const float* __restrict__ w1){
    int r = blockIdx.x, d = threadIdx.x;
    if (r < 128) g_embwT[r*EMB + d] = embw[d*128 + r];
    else         g_w1T[(r-128)*EMB + d] = w1[d*8 + (r-128)];
}

// ------------------- embedding conv as im2col GEMM + pos (32-token tiles) --
__global__ void __launch_bounds__(256) k_embed(const float* __restrict__ x,
                        const float* __restrict__ eb, const float* __restrict__ pos){
    int b = blockIdx.y, tile0 = blockIdx.x*32, tid = threadIdx.x, d = tid;
    __shared__ __align__(16) float X[32][128];
    for (int i = tid; i < 32*128; i += 256){
        int tt = i >> 7, ck = i & 127, c = ck >> 3, k = ck & 7;
        int n = tile0 + tt;
        X[tt][ck] = (n < N0) ? x[((size_t)b*16 + c)*LL + 4*n + k] : 0.f;
    }
    __syncthreads();
    float acc[32];
    #pragma unroll
    for (int t = 0; t < 32; t++) acc[t] = 0.f;
    for (int k4 = 0; k4 < 32; k4++){
        float w0 = g_embwT[(k4*4+0)*EMB + d];
        float w1v = g_embwT[(k4*4+1)*EMB + d];
        float w2v = g_embwT[(k4*4+2)*EMB + d];
        float w3v = g_embwT[(k4*4+3)*EMB + d];
        #pragma unroll
        for (int tt = 0; tt < 32; tt++){
            float4 xv = *(const float4*)&X[tt][k4*4];
            acc[tt] += xv.x*w0 + xv.y*w1v + xv.z*w2v + xv.w*w3v;
        }
    }
    float bv = eb[d];
    #pragma unroll
    for (int tt = 0; tt < 32; tt++){
        int n = tile0 + tt;
        if (n < N0) g_h[((size_t)b*N0 + n)*EMB + d] = acc[tt] + bv + pos[(size_t)n*EMB + d];
    }
}

// ---- warp-per-token: rmsnorm1 + attn MLP (+ MODE1: h=xn*sc, xn2=rmsnorm2) --
template<int MODE>
__global__ void k_norm_attn(const float* __restrict__ ng, const float* __restrict__ ng2,
                            const float* __restrict__ b1, const float* __restrict__ w2,
                            const float* __restrict__ b2, int N, int Ttot){
    int gw = (blockIdx.x*blockDim.x + threadIdx.x) >> 5;
    if (gw >= Ttot) return;
    int l = threadIdx.x & 31;
    size_t t = (size_t)gw;
    float v[8], xn[8];
    float s = 0.f;
    #pragma unroll
    for (int q = 0; q < 8; q++){ v[q] = g_h[t*EMB + l + 32*q]; s += v[q]*v[q]; }
    s = wsum_all(s);
    float inv = 16.0f / fmaxf(sqrtf(s), 1e-12f);
    #pragma unroll
    for (int q = 0; q < 8; q++) xn[q] = v[q]*inv*ng[l + 32*q];
    if (MODE == 0){
        #pragma unroll
        for (int q = 0; q < 8; q++) g_xn[t*EMB + l + 32*q] = xn[q];
    }
    float hp[8];
    #pragma unroll
    for (int j = 0; j < 8; j++){
        float a = 0.f;
        #pragma unroll
        for (int q = 0; q < 8; q++) a += xn[q]*g_w1T[j*EMB + l + 32*q];
        hp[j] = a;
    }
    #pragma unroll
    for (int j = 0; j < 8; j++) hp[j] = wsum_all(hp[j]);
    float sc = 0.f;
    if (l == 0){
        float s2 = b2[0];
        #pragma unroll
        for (int j = 0; j < 8; j++) s2 += tanhf(hp[j] + b1[j])*w2[j];
        sc = 1.0f/(1.0f + expf(-s2));
        int b = gw / N, n = gw - b*N;
        g_scores[b*1024 + n] = sc;
    }
    if (MODE == 1){
        sc = __shfl_sync(0xffffffffu, sc, 0);
        float hv[8]; float s3 = 0.f;
        #pragma unroll
        for (int q = 0; q < 8; q++){ hv[q] = xn[q]*sc; s3 += hv[q]*hv[q]; }
        s3 = wsum_all(s3);
        float inv2 = 16.0f / fmaxf(sqrtf(s3), 1e-12f);
        #pragma unroll
        for (int q = 0; q < 8; q++){
            size_t ix = t*EMB + l + 32*q;
            g_h[ix] = hv[q];
            g_xn2[ix] = hv[q]*inv2*ng2[l + 32*q];
        }
    }
}

// ---- warp-per-token attn on raw h -> end_scores ----------------------------
__global__ void k_attn_raw(const float* __restrict__ b1, const float* __restrict__ w2,
                           const float* __restrict__ b2){
    int gw = (blockIdx.x*blockDim.x + threadIdx.x) >> 5;
    if (gw >= T1) return;
    int l = threadIdx.x & 31;
    size_t t = (size_t)gw;
    float v[8];
    #pragma unroll
    for (int q = 0; q < 8; q++) v[q] = g_h[t*EMB + l + 32*q];
    float hp[8];
    #pragma unroll
    for (int j = 0; j < 8; j++){
        float a = 0.f;
        #pragma unroll
        for (int q = 0; q < 8; q++) a += v[q]*g_w1T[j*EMB + l + 32*q];
        hp[j] = a;
    }
    #pragma unroll
    for (int j = 0; j < 8; j++) hp[j] = wsum_all(hp[j]);
    if (l == 0){
        float s2 = b2[0];
        #pragma unroll
        for (int j = 0; j < 8; j++) s2 += tanhf(hp[j] + b1[j])*w2[j];
        g_escore[t] = 1.0f/(1.0f + expf(-s2));
    }
}

// ---------------- per-batch top-512 (bitonic 1024) + mask ------------------
__global__ void k_topk(){
    int b = blockIdx.x, tid = threadIdx.x;   // 512 threads
    __shared__ float v[1024];
    __shared__ int   ix[1024];
    __shared__ int   sel[K1];
    for (int i = tid; i < 1024; i += 512){
        v[i] = (i < N0) ? g_scores[b*1024 + i] : -1e30f;
        ix[i] = i;
    }
    __syncthreads();
    for (int k = 2; k <= 1024; k <<= 1){
        for (int j = k >> 1; j > 0; j >>= 1){
            for (int i = tid; i < 1024; i += 512){
                int p = i ^ j;
                if (p > i){
                    bool up = ((i & k) == 0);
                    if ((v[i] > v[p]) == up){
                        float tv = v[i]; v[i] = v[p]; v[p] = tv;
                        int ti = ix[i]; ix[i] = ix[p]; ix[p] = ti;
                    }
                }
            }
            __syncthreads();
        }
    }
    sel[tid] = ix[512 + tid];
    __syncthreads();
    for (int k = 2; k <= K1; k <<= 1){
        for (int j = k >> 1; j > 0; j >>= 1){
            int i = tid, p = i ^ j;
            if (p > i){
                bool up = ((i & k) == 0);
                if ((sel[i] > sel[p]) == up){ int tt = sel[i]; sel[i] = sel[p]; sel[p] = tt; }
            }
            __syncthreads();
        }
    }
    g_selidx[b*K1 + tid] = sel[tid];
    for (int i = tid; i < 1024; i += 512) g_mask[b*1024 + i] = 0;
    __syncthreads();
    g_mask[b*1024 + sel[tid]] = 1;
}

// ---- gather selected tokens + fused rmsnorm2 (warp-per-token) --------------
__global__ void k_gather(const float* __restrict__ ng2){
    int gw = (blockIdx.x*blockDim.x + threadIdx.x) >> 5;
    if (gw >= BB*K1) return;
    int l = threadIdx.x & 31;
    int b = gw / K1, j = gw - b*K1;
    int n = g_selidx[b*K1 + j];
    float sc = g_scores[b*1024 + n];
    const float* src = g_xn + ((size_t)b*N0 + n)*EMB;
    float hv[8]; float ss = 0.f;
    #pragma unroll
    for (int q = 0; q < 8; q++){ hv[q] = src[l + 32*q]*sc; ss += hv[q]*hv[q]; }
    ss = wsum_all(ss);
    float inv = 16.0f / fmaxf(sqrtf(ss), 1e-12f);
    size_t t = (size_t)b*N1 + j;
    #pragma unroll
    for (int q = 0; q < 8; q++){
        size_t ix = t*EMB + l + 32*q;
        g_h[ix] = hv[q];
        g_xn2[ix] = hv[q]*inv*ng2[l + 32*q];
    }
}

// ---- extra token (sum of unselected) + fused rmsnorm2 ----------------------
__global__ void k_extra(const float* __restrict__ ng2){
    int b = blockIdx.x, d = threadIdx.x;
    float acc = 0.f;
    const float* xb2 = g_xn + (size_t)b*N0*EMB;
    for (int n = 0; n < N0; n++)
        if (!g_mask[b*1024 + n]) acc += xb2[(size_t)n*EMB + d]*g_scores[b*1024 + n];
    __shared__ float red[8];
    __shared__ float sinv;
    float sq = wsum(acc*acc);
    if ((d & 31) == 0) red[d >> 5] = sq;
    __syncthreads();
    if (d == 0){
        float s = 0.f;
        #pragma unroll
        for (int i = 0; i < 8; i++) s += red[i];
        sinv = 16.0f / fmaxf(sqrtf(s), 1e-12f);
    }
    __syncthreads();
    size_t t = (size_t)b*N1 + K1;
    g_h[t*EMB + d] = acc;
    g_xn2[t*EMB + d] = acc*sinv*ng2[d];
}

// ---------------- MoE gate -------------------------------------------------
__global__ void k_zero(){ if (threadIdx.x < 4) g_ecnt[threadIdx.x] = 0; }

__global__ void k_gate(const float* __restrict__ gw, const float* __restrict__ gb){
    int tid = threadIdx.x, warp = tid >> 5, lane = tid & 31;
    int t = blockIdx.x*8 + warp;
    if (t >= T1) return;
    float s0 = 0.f, s1 = 0.f, s2 = 0.f, s3 = 0.f;
    const float4* gw4 = (const float4*)gw;
    #pragma unroll
    for (int q = 0; q < 8; q++){
        int dd = lane + 32*q;
        float xv = g_xn2[(size_t)t*EMB + dd];
        float4 g4 = gw4[dd];
        s0 += xv*g4.x; s1 += xv*g4.y; s2 += xv*g4.z; s3 += xv*g4.w;
    }
    s0 = wsum(s0); s1 = wsum(s1); s2 = wsum(s2); s3 = wsum(s3);
    if (lane == 0){
        float lg[4] = {s0+gb[0], s1+gb[1], s2+gb[2], s3+gb[3]};
        float mx = lg[0];
        #pragma unroll
        for (int e = 1; e < 4; e++) mx = fmaxf(mx, lg[e]);
        float ex[4], sum = 0.f;
        #pragma unroll
        for (int e = 0; e < 4; e++){ ex[e] = expf(lg[e]-mx); sum += ex[e]; }
        float inv = 1.0f/sum;
        int be = 0; float bp = ex[0];
        #pragma unroll
        for (int e = 1; e < 4; e++) if (ex[e] > bp){ bp = ex[e]; be = e; }
        #pragma unroll
        for (int e = 0; e < 4; e++) g_probs[(size_t)t*4 + e] = ex[e]*inv;
        g_topV[t] = bp*inv;
        int pos = atomicAdd(&g_ecnt[be], 1);   // list order irrelevant to values
        g_elist[be*T1 + pos] = t;
    }
}

__global__ void k_imp(){
    int e = blockIdx.x, tid = threadIdx.x;
    __shared__ float red[8];
    float acc = 0.f;
    for (int t = tid; t < T1; t += 256) acc += g_probs[(size_t)t*4 + e];
    acc = wsum(acc);
    if ((tid & 31) == 0) red[tid >> 5] = acc;
    __syncthreads();
    if (tid == 0){
        float s = 0.f;
        #pragma unroll
        for (int i = 0; i < 8; i++) s += red[i];
        g_imp[e] = s;
    }
}

// ---- fused routed expert: out2 = gelu(X@W1+b1)@W2+b2 (32-token tiles) -----
__global__ void __launch_bounds__(256) k_expert2(const float* __restrict__ W1,
                        const float* __restrict__ B1, const float* __restrict__ W2,
                        const float* __restrict__ B2){
    int e = blockIdx.y;
    int cnt = g_ecnt[e];
    int base = blockIdx.x*32;
    if (base >= cnt) return;
    int m = min(32, cnt - base);
    __shared__ __align__(16) float X[32][EMB];
    __shared__ int tl[32];
    int d = threadIdx.x;
    if (d < 32) tl[d] = (base + d < cnt) ? g_elist[e*T1 + base + d] : 0;
    __syncthreads();
    for (int tt = 0; tt < 32; tt++)
        X[tt][d] = (tt < m) ? g_xn2[(size_t)tl[tt]*EMB + d] : 0.f;
    __syncthreads();
    float acc[32];
    #pragma unroll
    for (int i = 0; i < 32; i++) acc[i] = 0.f;
    const float* Wd = W1 + (size_t)e*EMB*EMB + d;
    for (int k4 = 0; k4 < EMB/4; k4++){
        float w0 = Wd[(size_t)(k4*4+0)*EMB];
        float w1v = Wd[(size_t)(k4*4+1)*EMB];
        float w2v = Wd[(size_t)(k4*4+2)*EMB];
        float w3v = Wd[(size_t)(k4*4+3)*EMB];
        #pragma unroll
        for (int tt = 0; tt < 32; tt++){
            float4 xv = *(const float4*)&X[tt][k4*4];
            acc[tt] += xv.x*w0 + xv.y*w1v + xv.z*w2v + xv.w*w3v;
        }
    }
    float b1v = B1[e*EMB + d];
    __syncthreads();
    #pragma unroll
    for (int tt = 0; tt < 32; tt++) X[tt][d] = geluf(acc[tt] + b1v);
    __syncthreads();
    #pragma unroll
    for (int i = 0; i < 32; i++) acc[i] = 0.f;
    const float* Wd2 = W2 + (size_t)e*EMB*EMB + d;
    for (int k4 = 0; k4 < EMB/4; k4++){
        float w0 = Wd2[(size_t)(k4*4+0)*EMB];
        float w1v = Wd2[(size_t)(k4*4+1)*EMB];
        float w2v = Wd2[(size_t)(k4*4+2)*EMB];
        float w3v = Wd2[(size_t)(k4*4+3)*EMB];
        #pragma unroll
        for (int tt = 0; tt < 32; tt++){
            float4 xv = *(const float4*)&X[tt][k4*4];
            acc[tt] += xv.x*w0 + xv.y*w1v + xv.z*w2v + xv.w*w3v;
        }
    }
    float b2v = B2[e*EMB + d];
    for (int tt = 0; tt < m; tt++)
        g_out2[(size_t)tl[tt]*EMB + d] = acc[tt] + b2v;
}

// ---- MoE combine: h += gelu(rmsnorm(xn2 + out2*topV)) (warp-per-token) ----
__global__ void k_moe_combine(const float* __restrict__ gamma){
    int gw = (blockIdx.x*blockDim.x + threadIdx.x) >> 5;
    if (gw >= T1) return;
    int l = threadIdx.x & 31;
    size_t t = (size_t)gw;
    float tv = g_topV[t];
    float v[8]; float ss = 0.f;
    #pragma unroll
    for (int q = 0; q < 8; q++){
        size_t ix = t*EMB + l + 32*q;
        v[q] = g_xn2[ix] + g_out2[ix]*tv;
        ss += v[q]*v[q];
    }
    ss = wsum_all(ss);
    float inv = 16.0f / fmaxf(sqrtf(ss), 1e-12f);
    #pragma unroll
    for (int q = 0; q < 8; q++){
        size_t ix = t*EMB + l + 32*q;
        g_h[ix] += geluf(v[q]*inv*gamma[l + 32*q]);
    }
}

// ---------------- inception: bottleneck 1x1 + maxpool->1x1 -----------------
__global__ void k_bott(const float* __restrict__ bw, const float* __restrict__ mw,
                       const float* __restrict__ bng, const float* __restrict__ bnb,
                       int N){
    int b = blockIdx.y, tile0 = blockIdx.x*32, tid = threadIdx.x;
    __shared__ float sm[34][EMB];
    __shared__ float wbs[32][33], wms[32][33];
    for (int i = tid; i < 34*EMB; i += 256){
        int p = i >> 8, d = i & 255;
        int n = tile0 + p - 1;
        sm[p][d] = (n >= 0 && n < N) ? g_xn2[((size_t)b*N + n)*EMB + d] : -1e30f;
    }
    int f = tid & 31, grp = tid >> 5, p1 = grp*4 + 1;
    float ab[4] = {0,0,0,0}, am[4] = {0,0,0,0};
    for (int ch = 0; ch < 8; ch++){
        __syncthreads();
        for (int i = tid; i < 1024; i += 256){
            int ff = i >> 5, dd = i & 31;
            wbs[ff][dd] = bw[ff*EMB + ch*32 + dd];
            wms[ff][dd] = mw[ff*EMB + ch*32 + dd];
        }
        __syncthreads();
        #pragma unroll 4
        for (int dd = 0; dd < 32; dd++){
            int d = ch*32 + dd;
            float w_b = wbs[f][dd], w_m = wms[f][dd];
            float s0 = sm[p1-1][d], s1 = sm[p1][d], s2 = sm[p1+1][d];
            float s3 = sm[p1+2][d], s4 = sm[p1+3][d], s5 = sm[p1+4][d];
            ab[0] += s1*w_b; ab[1] += s2*w_b; ab[2] += s3*w_b; ab[3] += s4*w_b;
            am[0] += fmaxf(fmaxf(s0,s1),s2)*w_m;
            am[1] += fmaxf(fmaxf(s1,s2),s3)*w_m;
            am[2] += fmaxf(fmaxf(s2,s3),s4)*w_m;
            am[3] += fmaxf(fmaxf(s3,s4),s5)*w_m;
        }
    }
    float bsc = rsqrtf(1.0f + 1e-5f);
    float sc = bng[96+f]*bsc, bi = bnb[96+f];
    #pragma unroll
    for (int tt = 0; tt < 4; tt++){
        int n = tile0 + grp*4 + tt;
        if (n < N){
            g_xbT[((size_t)b*32 + f)*1024 + n] = ab[tt];
            g_act[((size_t)b*N + n)*128 + 96 + f] = geluf(am[tt]*sc + bi);
        }
    }
}

// ---- inception convs: 128-pos tiles, 512 threads, 8 pos/thread ------------
__global__ void __launch_bounds__(512) k_convs(const float* __restrict__ w39,
                        const float* __restrict__ w19, const float* __restrict__ w9,
                        const float* __restrict__ bng, const float* __restrict__ bnb,
                        int N){
    int b = blockIdx.y, tile0 = blockIdx.x*128, tid = threadIdx.x;
    __shared__ float sm[32][166];
    __shared__ float ws[32][69];
    for (int i = tid; i < 32*166; i += 512){
        int g = i/166, p = i - g*166;
        int n = tile0 + p - 19;
        sm[g][p] = (n >= 0 && n < N) ? g_xbT[((size_t)b*32 + g)*1024 + n] : 0.f;
    }
    int f = tid & 31, grp = tid >> 5;     // 16 position groups
    int pos0 = grp*8;
    float a39[8], a19[8], a9[8];
    #pragma unroll
    for (int j = 0; j < 8; j++){ a39[j]=0.f; a19[j]=0.f; a9[j]=0.f; }
    for (int g = 0; g < 32; g++){
        __syncthreads();
        for (int i = tid; i < 32*67; i += 512){
            int ff = i/67, j = i - ff*67;
            float wv = (j < 39) ? w39[ff*1248 + g*39 + j]
                     : (j < 58) ? w19[ff*608 + g*19 + (j-39)]
                                : w9[ff*288 + g*9 + (j-58)];
            ws[ff][j] = wv;
        }
        __syncthreads();
        {   // conv39, window base pos0
            float xw[7];
            #pragma unroll
            for (int j = 0; j < 7; j++) xw[j] = sm[g][pos0 + j];
            #pragma unroll
            for (int k = 0; k < 39; k++){
                float xn_ = sm[g][pos0 + k + 7];
                float w = ws[f][k];
                a39[0]+=xw[0]*w; a39[1]+=xw[1]*w; a39[2]+=xw[2]*w; a39[3]+=xw[3]*w;
                a39[4]+=xw[4]*w; a39[5]+=xw[5]*w; a39[6]+=xw[6]*w; a39[7]+=xn_*w;
                #pragma unroll
                for (int j = 0; j < 6; j++) xw[j] = xw[j+1];
                xw[6] = xn_;
            }
        }
        {   // conv19, window base pos0+10
            float xw[7];
            #pragma unroll
            for (int j = 0; j < 7; j++) xw[j] = sm[g][pos0 + 10 + j];
            #pragma unroll
            for (int k = 0; k < 19; k++){
                float xn_ = sm[g][pos0 + 10 + k + 7];
                float w = ws[f][39 + k];
                a19[0]+=xw[0]*w; a19[1]+=xw[1]*w; a19[2]+=xw[2]*w; a19[3]+=xw[3]*w;
                a19[4]+=xw[4]*w; a19[5]+=xw[5]*w; a19[6]+=xw[6]*w; a19[7]+=xn_*w;
                #pragma unroll
                for (int j = 0; j < 6; j++) xw[j] = xw[j+1];
                xw[6] = xn_;
            }
        }
        {   // conv9, window base pos0+15
            float xw[7];
            #pragma unroll
            for (int j = 0; j < 7; j++) xw[j] = sm[g][pos0 + 15 + j];
            #pragma unroll
            for (int k = 0; k < 9; k++){
                float xn_ = sm[g][pos0 + 15 + k + 7];
                float w = ws[f][58 + k];
                a9[0]+=xw[0]*w; a9[1]+=xw[1]*w; a9[2]+=xw[2]*w; a9[3]+=xw[3]*w;
                a9[4]+=xw[4]*w; a9[5]+=xw[5]*w; a9[6]+=xw[6]*w; a9[7]+=xn_*w;
                #pragma unroll
                for (int j = 0; j < 6; j++) xw[j] = xw[j+1];
                xw[6] = xn_;
            }
        }
    }
    float bsc = rsqrtf(1.0f + 1e-5f);
    float sc0 = bng[f]*bsc,    bi0 = bnb[f];
    float sc1 = bng[32+f]*bsc, bi1 = bnb[32+f];
    float sc2 = bng[64+f]*bsc, bi2 = bnb[64+f];
    #pragma unroll
    for (int tt = 0; tt < 8; tt++){
        int n = tile0 + pos0 + tt;
        if (n < N){
            size_t base = ((size_t)b*N + n)*128;
            g_act[base + f]      = geluf(a39[tt]*sc0 + bi0);
            g_act[base + 32 + f] = geluf(a19[tt]*sc1 + bi1);
            g_act[base + 64 + f] = geluf(a9[tt]*sc2 + bi2);
        }
    }
}

// ---- projection (32-token tiles): h (+)= act@W + b ; optional gelu --------
template<bool GACT>
__global__ void __launch_bounds__(256) k_proj(const float* __restrict__ W,
                        const float* __restrict__ bias, int T){
    int base = blockIdx.x*32, tid = threadIdx.x, d = tid;
    __shared__ __align__(16) float X[32][128];
    for (int i = tid; i < 32*128; i += 256){
        int tt = i >> 7, kk = i & 127;
        int t = base + tt;
        X[tt][kk] = (t < T) ? g_act[(size_t)t*128 + kk] : 0.f;
    }
    __syncthreads();
    float acc[32];
    #pragma unroll
    for (int i = 0; i < 32; i++) acc[i] = 0.f;
    for (int k4 = 0; k4 < 32; k4++){
        float w0 = W[(k4*4+0)*EMB + d];
        float w1v = W[(k4*4+1)*EMB + d];
        float w2v = W[(k4*4+2)*EMB + d];
        float w3v = W[(k4*4+3)*EMB + d];
        #pragma unroll
        for (int tt = 0; tt < 32; tt++){
            float4 xv = *(const float4*)&X[tt][k4*4];
            acc[tt] += xv.x*w0 + xv.y*w1v + xv.z*w2v + xv.w*w3v;
        }
    }
    float bv = bias[d];
    for (int tt = 0; tt < 32; tt++){
        int t = base + tt;
        if (t < T){
            float v = g_h[(size_t)t*EMB + d] + acc[tt] + bv;
            g_h[(size_t)t*EMB + d] = GACT ? geluf(v) : v;
        }
    }
}

// ---- final head: partials over token chunks, then deterministic combine ---
__global__ void k_final_part(const float* __restrict__ hw, const float* __restrict__ hb){
    int b = blockIdx.x, c = blockIdx.y;
    int tid = threadIdx.x, w = tid >> 5, l = tid & 31;
    __shared__ float s_hw[EMB];
    __shared__ float wacc[8];
    s_hw[tid] = hw[tid];
    __syncthreads();
    int j0 = c*65, j1 = min(j0 + 65, N1);
    float local = 0.f, hbias = hb[0];
    for (int j = j0 + w; j < j1; j += 8){
        size_t t = (size_t)b*N1 + j;
        float s = 0.f;
        #pragma unroll
        for (int q = 0; q < 8; q++){
            int d = l + 32*q;
            s += geluf(g_h[t*EMB + d])*s_hw[d];
        }
        s = wsum(s);
        if (l == 0) local += (s + hbias)*g_escore[t];
    }
    if (l == 0) wacc[w] = local;
    __syncthreads();
    if (tid == 0){
        float tot = 0.f;
        #pragma unroll
        for (int i = 0; i < 8; i++) tot += wacc[i];
        g_part[b*8 + c] = tot;
    }
}

__global__ void k_final_comb(float* __restrict__ out, int out_size){
    int b = threadIdx.x;
    if (b < BB){
        float s = 0.f;
        #pragma unroll
        for (int c = 0; c < 8; c++) s += g_part[b*8 + c];
        out[b] = s/(float)N1;
    }
    if (b == 0 && out_size > BB){
        float m = (g_imp[0]+g_imp[1]+g_imp[2]+g_imp[3])*0.25f;
        float v = 0.f;
        #pragma unroll
        for (int e = 0; e < 4; e++){ float dv = g_imp[e]-m; v += dv*dv; }
        v *= (1.0f/3.0f);
        out[BB] = v/(m*m + 1e-10f);
    }
}

// ---------------------------------------------------------------------------
extern "C" void kernel_launch(void* const* d_in, const int* in_sizes, int n_in,
                              void* d_out, int out_size){
    const float* x       = (const float*)d_in[0];
    const float* emb_w   = (const float*)d_in[3];
    const float* emb_b   = (const float*)d_in[4];
    const float* pos     = (const float*)d_in[5];
    const float* aw1     = (const float*)d_in[6];
    const float* ab1     = (const float*)d_in[7];
    const float* aw2     = (const float*)d_in[8];
    const float* ab2     = (const float*)d_in[9];
    const float* gw      = (const float*)d_in[10];
    const float* gb      = (const float*)d_in[11];
    const float* ew1     = (const float*)d_in[12];
    const float* eb1     = (const float*)d_in[13];
    const float* ew2     = (const float*)d_in[14];
    const float* eb2     = (const float*)d_in[15];
    const float* mgam    = (const float*)d_in[16];
    const float* n1g     = (const float*)d_in[17];
    const float* n2g     = (const float*)d_in[18];
    const float* bott    = (const float*)d_in[19];
    const float* w39     = (const float*)d_in[20];
    const float* w19     = (const float*)d_in[21];
    const float* w9      = (const float*)d_in[22];
    const float* mpw     = (const float*)d_in[23];
    const float* bng     = (const float*)d_in[24];
    const float* bnb     = (const float*)d_in[25];
    const float* pw      = (const float*)d_in[26];
    const float* pb      = (const float*)d_in[27];
    const float* hw      = (const float*)d_in[28];
    const float* hb      = (const float*)d_in[29];
    float* out = (float*)d_out;

    k_prep<<<136, 256>>>(emb_w, aw1);
    k_embed<<<dim3(32, BB), 256>>>(x, emb_b, pos);

    // ---- layer 0 (dense): fused norm1+attn+scale+norm2; incep; proj+gelu
    k_norm_attn<1><<<(BB*N0)/8, 256>>>(n1g, n2g, ab1, aw2, ab2, N0, BB*N0);
    k_bott<<<dim3(32, BB), 256>>>(bott, mpw, bng, bnb, N0);
    k_convs<<<dim3(8, BB), 512>>>(w39, w19, w9, bng, bnb, N0);
    k_proj<true><<<(BB*N0 + 31)/32, 256>>>(pw, pb, BB*N0);

    // ---- layer 1 (sparse, ratio 0.5)
    k_norm_attn<0><<<(BB*N0)/8, 256>>>(n1g + EMB, n2g, ab1, aw2, ab2, N0, BB*N0);
    k_topk<<<BB, 512>>>();
    k_gather<<<(BB*K1)/8, 256>>>(n2g + EMB);
    k_extra<<<BB, 256>>>(n2g + EMB);
    // MoE
    k_zero<<<1, 32>>>();
    k_gate<<<(T1 + 7)/8, 256>>>(gw, gb);
    k_imp<<<4, 256>>>();
    k_expert2<<<dim3((T1 + 31)/32, 4), 256>>>(ew1, eb1, ew2, eb2);
    k_moe_combine<<<(T1 + 7)/8, 256>>>(mgam);
    // Inception branch (layer-1 weights)
    k_bott<<<dim3((N1 + 31)/32, BB), 256>>>(bott + 32*EMB, mpw + 32*EMB,
                                            bng + 128, bnb + 128, N1);
    k_convs<<<dim3((N1 + 127)/128, BB), 512>>>(w39 + 32*32*39, w19 + 32*32*19,
                                               w9 + 32*32*9, bng + 128, bnb + 128, N1);
    k_proj<false><<<(T1 + 31)/32, 256>>>(pw + 128*EMB, pb + EMB, T1);
    // end_scores on pre-gelu h; fused gelu+head+mean in final
    k_attn_raw<<<(T1 + 7)/8, 256>>>(ab1, aw2, ab2);
    k_final_part<<<dim3(BB, 8), 256>>>(hw, hb);
    k_final_comb<<<1, 64>>>(out, out_size);
}

// round 17
// speedup vs baseline: 1.4830x; 1.2513x over previous
#include <cuda_runtime.h>
#include <math.h>

#define BB 64
#define LL 4096
#define N0 1023
#define K1 512
#define N1 513
#define T1 (BB*N1)
#define EMB 256

// ------------------------- device scratch (no allocs) ----------------------
static __device__ float g_h[BB*N0*EMB];
static __device__ float g_xn[BB*N0*EMB];
static __device__ float g_xn2[BB*N0*EMB];
static __device__ float g_scores[BB*1024];
static __device__ float g_xbT[BB*32*1024];
static __device__ float g_act[BB*N0*128];
static __device__ float g_out2[T1*EMB];
static __device__ float g_probs[T1*4];
static __device__ float g_topV[T1];
static __device__ int   g_selidx[BB*K1];
static __device__ unsigned char g_mask[BB*1024];
static __device__ int   g_elist[4*T1];
static __device__ int   g_ecnt[4];
static __device__ float g_imp[4];
static __device__ float g_embwT[128*EMB];
static __device__ float g_w1T[8*EMB];
static __device__ float g_part[BB*8];
static __device__ float g_epart[BB*8*EMB];

__device__ __forceinline__ float geluf(float x){
    return 0.5f*x*(1.0f + erff(x*0.70710678118654752440f));
}
__device__ __forceinline__ float wsum(float v){
    #pragma unroll
    for (int o = 16; o > 0; o >>= 1) v += __shfl_down_sync(0xffffffffu, v, o);
    return v;
}
__device__ __forceinline__ float wsum_all(float v){
    #pragma unroll
    for (int o = 16; o > 0; o >>= 1) v += __shfl_xor_sync(0xffffffffu, v, o);
    return v;
}

// ---- shared GEMM core: 16 tokens x 4 outputs per thread --------------------
// W: [K][256] row-major. Xs: [64][K] smem. og in [0,64), tg in [0,4).
template<int K4>
__device__ __forceinline__ void gemm16x4(const float* __restrict__ W,
                                         const float* Xs, int og, int tg,
                                         float (&acc)[16][4]){
    const float4* __restrict__ W4 = (const float4*)W;
    const float4* X4 = (const float4*)Xs;
    #pragma unroll
    for (int i = 0; i < 16; i++)
        #pragma unroll
        for (int j = 0; j < 4; j++) acc[i][j] = 0.f;
    #pragma unroll 2
    for (int k4 = 0; k4 < K4; k4++){
        float4 w0 = W4[(size_t)(k4*4+0)*64 + og];
        float4 w1 = W4[(size_t)(k4*4+1)*64 + og];
        float4 w2 = W4[(size_t)(k4*4+2)*64 + og];
        float4 w3 = W4[(size_t)(k4*4+3)*64 + og];
        #pragma unroll
        for (int tt = 0; tt < 16; tt++){
            float4 xv = X4[(tg*16+tt)*K4 + k4];
            acc[tt][0] = fmaf(xv.w,w3.x,fmaf(xv.z,w2.x,fmaf(xv.y,w1.x,fmaf(xv.x,w0.x,acc[tt][0]))));
            acc[tt][1] = fmaf(xv.w,w3.y,fmaf(xv.z,w2.y,fmaf(xv.y,w1.y,fmaf(xv.x,w0.y,acc[tt][1]))));
            acc[tt][2] = fmaf(xv.w,w3.z,fmaf(xv.z,w2.z,fmaf(xv.y,w1.z,fmaf(xv.x,w0.z,acc[tt][2]))));
            acc[tt][3] = fmaf(xv.w,w3.w,fmaf(xv.z,w2.w,fmaf(xv.y,w1.w,fmaf(xv.x,w0.w,acc[tt][3]))));
        }
    }
}

// ------------------- weight pre-transpose ----------------------------------
__global__ void k_prep(const float* __restrict__ embw, const float* __restrict__ w1){
    int r = blockIdx.x, d = threadIdx.x;
    if (r < 128) g_embwT[r*EMB + d] = embw[d*128 + r];
    else         g_w1T[(r-128)*EMB + d] = w1[d*8 + (r-128)];
}

// ------------------- embedding conv as im2col GEMM + pos (64-token tiles) --
__global__ void __launch_bounds__(256) k_embed(const float* __restrict__ x,
                        const float* __restrict__ eb, const float* __restrict__ pos){
    int b = blockIdx.y, tile0 = blockIdx.x*64, tid = threadIdx.x;
    int og = tid & 63, tg = tid >> 6;
    __shared__ __align__(16) float X[64*128];
    for (int i = tid; i < 64*128; i += 256){
        int tt = i >> 7, ck = i & 127, c = ck >> 3, kk = ck & 7;
        int n = tile0 + tt;
        X[i] = (n < N0) ? x[((size_t)b*16 + c)*LL + 4*n + kk] : 0.f;
    }
    __syncthreads();
    float acc[16][4];
    gemm16x4<32>(g_embwT, X, og, tg, acc);
    float4 ebv = ((const float4*)eb)[og];
    #pragma unroll
    for (int tt = 0; tt < 16; tt++){
        int n = tile0 + tg*16 + tt;
        if (n < N0){
            float4 pv = ((const float4*)pos)[(size_t)n*64 + og];
            float4 o;
            o.x = acc[tt][0] + ebv.x + pv.x;
            o.y = acc[tt][1] + ebv.y + pv.y;
            o.z = acc[tt][2] + ebv.z + pv.z;
            o.w = acc[tt][3] + ebv.w + pv.w;
            ((float4*)g_h)[((size_t)b*N0 + n)*64 + og] = o;
        }
    }
}

// ---- warp-per-token: rmsnorm1 + attn MLP (+ MODE1: h=xn*sc, xn2=rmsnorm2) --
template<int MODE>
__global__ void k_norm_attn(const float* __restrict__ ng, const float* __restrict__ ng2,
                            const float* __restrict__ b1, const float* __restrict__ w2,
                            const float* __restrict__ b2, int N, int Ttot){
    int gw = (blockIdx.x*blockDim.x + threadIdx.x) >> 5;
    if (gw >= Ttot) return;
    int l = threadIdx.x & 31;
    size_t t = (size_t)gw;
    float v[8], xn[8];
    float s = 0.f;
    #pragma unroll
    for (int q = 0; q < 8; q++){ v[q] = g_h[t*EMB + l + 32*q]; s += v[q]*v[q]; }
    s = wsum_all(s);
    float inv = 16.0f / fmaxf(sqrtf(s), 1e-12f);
    #pragma unroll
    for (int q = 0; q < 8; q++) xn[q] = v[q]*inv*ng[l + 32*q];
    if (MODE == 0){
        #pragma unroll
        for (int q = 0; q < 8; q++) g_xn[t*EMB + l + 32*q] = xn[q];
    }
    float hp[8];
    #pragma unroll
    for (int j = 0; j < 8; j++){
        float a = 0.f;
        #pragma unroll
        for (int q = 0; q < 8; q++) a += xn[q]*g_w1T[j*EMB + l + 32*q];
        hp[j] = a;
    }
    #pragma unroll
    for (int j = 0; j < 8; j++) hp[j] = wsum_all(hp[j]);
    float sc = 0.f;
    if (l == 0){
        float s2 = b2[0];
        #pragma unroll
        for (int j = 0; j < 8; j++) s2 += tanhf(hp[j] + b1[j])*w2[j];
        sc = 1.0f/(1.0f + expf(-s2));
        int b = gw / N, n = gw - b*N;
        g_scores[b*1024 + n] = sc;
    }
    if (MODE == 1){
        sc = __shfl_sync(0xffffffffu, sc, 0);
        float hv[8]; float s3 = 0.f;
        #pragma unroll
        for (int q = 0; q < 8; q++){ hv[q] = xn[q]*sc; s3 += hv[q]*hv[q]; }
        s3 = wsum_all(s3);
        float inv2 = 16.0f / fmaxf(sqrtf(s3), 1e-12f);
        #pragma unroll
        for (int q = 0; q < 8; q++){
            size_t ix = t*EMB + l + 32*q;
            g_h[ix] = hv[q];
            g_xn2[ix] = hv[q]*inv2*ng2[l + 32*q];
        }
    }
}

// ---------------- per-batch top-512 (bitonic 1024) + mask ------------------
__global__ void k_topk(){
    int b = blockIdx.x, tid = threadIdx.x;   // 512 threads
    __shared__ float v[1024];
    __shared__ int   ix[1024];
    __shared__ int   sel[K1];
    for (int i = tid; i < 1024; i += 512){
        v[i] = (i < N0) ? g_scores[b*1024 + i] : -1e30f;
        ix[i] = i;
    }
    __syncthreads();
    for (int k = 2; k <= 1024; k <<= 1){
        for (int j = k >> 1; j > 0; j >>= 1){
            for (int i = tid; i < 1024; i += 512){
                int p = i ^ j;
                if (p > i){
                    bool up = ((i & k) == 0);
                    if ((v[i] > v[p]) == up){
                        float tv = v[i]; v[i] = v[p]; v[p] = tv;
                        int ti = ix[i]; ix[i] = ix[p]; ix[p] = ti;
                    }
                }
            }
            __syncthreads();
        }
    }
    sel[tid] = ix[512 + tid];
    __syncthreads();
    for (int k = 2; k <= K1; k <<= 1){
        for (int j = k >> 1; j > 0; j >>= 1){
            int i = tid, p = i ^ j;
            if (p > i){
                bool up = ((i & k) == 0);
                if ((sel[i] > sel[p]) == up){ int tt = sel[i]; sel[i] = sel[p]; sel[p] = tt; }
            }
            __syncthreads();
        }
    }
    g_selidx[b*K1 + tid] = sel[tid];
    for (int i = tid; i < 1024; i += 512) g_mask[b*1024 + i] = 0;
    __syncthreads();
    g_mask[b*1024 + sel[tid]] = 1;
}

// ---- gather selected tokens + fused rmsnorm2 (warp-per-token) --------------
__global__ void k_gather(const float* __restrict__ ng2){
    int gw = (blockIdx.x*blockDim.x + threadIdx.x) >> 5;
    if (gw >= BB*K1) return;
    int l = threadIdx.x & 31;
    int b = gw / K1, j = gw - b*K1;
    int n = g_selidx[b*K1 + j];
    float sc = g_scores[b*1024 + n];
    const float* src = g_xn + ((size_t)b*N0 + n)*EMB;
    float hv[8]; float ss = 0.f;
    #pragma unroll
    for (int q = 0; q < 8; q++){ hv[q] = src[l + 32*q]*sc; ss += hv[q]*hv[q]; }
    ss = wsum_all(ss);
    float inv = 16.0f / fmaxf(sqrtf(ss), 1e-12f);
    size_t t = (size_t)b*N1 + j;
    #pragma unroll
    for (int q = 0; q < 8; q++){
        size_t ix = t*EMB + l + 32*q;
        g_h[ix] = hv[q];
        g_xn2[ix] = hv[q]*inv*ng2[l + 32*q];
    }
}

// ---- extra token: 8 fixed partials per batch, then combine -----------------
__global__ void k_extra_part(){
    int b = blockIdx.x, c = blockIdx.y, d = threadIdx.x;
    int n0 = c*128, n1 = min(n0 + 128, N0);
    float acc = 0.f;
    for (int n = n0; n < n1; n++)
        if (!g_mask[b*1024 + n]) acc += g_xn[((size_t)b*N0 + n)*EMB + d]*g_scores[b*1024 + n];
    g_epart[((size_t)b*8 + c)*EMB + d] = acc;
}

__global__ void k_extra_comb(const float* __restrict__ ng2){
    int b = blockIdx.x, d = threadIdx.x;
    float acc = 0.f;
    #pragma unroll
    for (int c = 0; c < 8; c++) acc += g_epart[((size_t)b*8 + c)*EMB + d];
    __shared__ float red[8];
    __shared__ float sinv;
    float sq = wsum(acc*acc);
    if ((d & 31) == 0) red[d >> 5] = sq;
    __syncthreads();
    if (d == 0){
        float s = 0.f;
        #pragma unroll
        for (int i = 0; i < 8; i++) s += red[i];
        sinv = 16.0f / fmaxf(sqrtf(s), 1e-12f);
    }
    __syncthreads();
    size_t t = (size_t)b*N1 + K1;
    g_h[t*EMB + d] = acc;
    g_xn2[t*EMB + d] = acc*sinv*ng2[d];
}

// ---------------- MoE gate -------------------------------------------------
__global__ void k_zero(){ if (threadIdx.x < 4) g_ecnt[threadIdx.x] = 0; }

__global__ void k_gate(const float* __restrict__ gw, const float* __restrict__ gb){
    int tid = threadIdx.x, warp = tid >> 5, lane = tid & 31;
    int t = blockIdx.x*8 + warp;
    if (t >= T1) return;
    float s0 = 0.f, s1 = 0.f, s2 = 0.f, s3 = 0.f;
    const float4* gw4 = (const float4*)gw;
    #pragma unroll
    for (int q = 0; q < 8; q++){
        int dd = lane + 32*q;
        float xv = g_xn2[(size_t)t*EMB + dd];
        float4 g4 = gw4[dd];
        s0 += xv*g4.x; s1 += xv*g4.y; s2 += xv*g4.z; s3 += xv*g4.w;
    }
    s0 = wsum(s0); s1 = wsum(s1); s2 = wsum(s2); s3 = wsum(s3);
    if (lane == 0){
        float lg[4] = {s0+gb[0], s1+gb[1], s2+gb[2], s3+gb[3]};
        float mx = lg[0];
        #pragma unroll
        for (int e = 1; e < 4; e++) mx = fmaxf(mx, lg[e]);
        float ex[4], sum = 0.f;
        #pragma unroll
        for (int e = 0; e < 4; e++){ ex[e] = expf(lg[e]-mx); sum += ex[e]; }
        float inv = 1.0f/sum;
        int be = 0; float bp = ex[0];
        #pragma unroll
        for (int e = 1; e < 4; e++) if (ex[e] > bp){ bp = ex[e]; be = e; }
        #pragma unroll
        for (int e = 0; e < 4; e++) g_probs[(size_t)t*4 + e] = ex[e]*inv;
        g_topV[t] = bp*inv;
        int pos = atomicAdd(&g_ecnt[be], 1);   // list order irrelevant to values
        g_elist[be*T1 + pos] = t;
    }
}

__global__ void k_imp(){
    int e = blockIdx.x, tid = threadIdx.x;
    __shared__ float red[8];
    float acc = 0.f;
    for (int t = tid; t < T1; t += 256) acc += g_probs[(size_t)t*4 + e];
    acc = wsum(acc);
    if ((tid & 31) == 0) red[tid >> 5] = acc;
    __syncthreads();
    if (tid == 0){
        float s = 0.f;
        #pragma unroll
        for (int i = 0; i < 8; i++) s += red[i];
        g_imp[e] = s;
    }
}

// ---- fused routed expert: out2 = gelu(X@W1+b1)@W2+b2 (64-token tiles) -----
__global__ void __launch_bounds__(256) k_expert2(const float* __restrict__ W1,
                        const float* __restrict__ B1, const float* __restrict__ W2,
                        const float* __restrict__ B2){
    extern __shared__ __align__(16) float X[];   // 64*256 floats
    __shared__ int tl[64];
    int e = blockIdx.y;
    int cnt = g_ecnt[e];
    int base = blockIdx.x*64;
    if (base >= cnt) return;
    int m = min(64, cnt - base);
    int tid = threadIdx.x, og = tid & 63, tg = tid >> 6;
    if (tid < 64) tl[tid] = (base + tid < cnt) ? g_elist[e*T1 + base + tid] : 0;
    __syncthreads();
    for (int i = tid; i < 64*256; i += 256){
        int tt = i >> 8, k = i & 255;
        X[i] = (tt < m) ? g_xn2[(size_t)tl[tt]*EMB + k] : 0.f;
    }
    __syncthreads();
    float acc[16][4];
    gemm16x4<64>(W1 + (size_t)e*EMB*EMB, X, og, tg, acc);
    float4 b1v = ((const float4*)(B1 + e*EMB))[og];
    __syncthreads();
    #pragma unroll
    for (int tt = 0; tt < 16; tt++){
        float4 g4;
        g4.x = geluf(acc[tt][0] + b1v.x);
        g4.y = geluf(acc[tt][1] + b1v.y);
        g4.z = geluf(acc[tt][2] + b1v.z);
        g4.w = geluf(acc[tt][3] + b1v.w);
        ((float4*)X)[(tg*16+tt)*64 + og] = g4;
    }
    __syncthreads();
    gemm16x4<64>(W2 + (size_t)e*EMB*EMB, X, og, tg, acc);
    float4 b2v = ((const float4*)(B2 + e*EMB))[og];
    #pragma unroll
    for (int tt = 0; tt < 16; tt++){
        int row = tg*16 + tt;
        if (row < m){
            float4 o;
            o.x = acc[tt][0] + b2v.x;
            o.y = acc[tt][1] + b2v.y;
            o.z = acc[tt][2] + b2v.z;
            o.w = acc[tt][3] + b2v.w;
            ((float4*)g_out2)[(size_t)tl[row]*64 + og] = o;
        }
    }
}

// ---- MoE combine: h += gelu(rmsnorm(xn2 + out2*topV)) (warp-per-token) ----
__global__ void k_moe_combine(const float* __restrict__ gamma){
    int gw = (blockIdx.x*blockDim.x + threadIdx.x) >> 5;
    if (gw >= T1) return;
    int l = threadIdx.x & 31;
    size_t t = (size_t)gw;
    float tv = g_topV[t];
    float v[8]; float ss = 0.f;
    #pragma unroll
    for (int q = 0; q < 8; q++){
        size_t ix = t*EMB + l + 32*q;
        v[q] = g_xn2[ix] + g_out2[ix]*tv;
        ss += v[q]*v[q];
    }
    ss = wsum_all(ss);
    float inv = 16.0f / fmaxf(sqrtf(ss), 1e-12f);
    #pragma unroll
    for (int q = 0; q < 8; q++){
        size_t ix = t*EMB + l + 32*q;
        g_h[ix] += geluf(v[q]*inv*gamma[l + 32*q]);
    }
}

// ---- inception: bottleneck 1x1 + maxpool->1x1, maxpool precomputed --------
__global__ void __launch_bounds__(256) k_bott(const float* __restrict__ bw,
                       const float* __restrict__ mw, const float* __restrict__ bng,
                       const float* __restrict__ bnb, int N){
    int b = blockIdx.y, tile0 = blockIdx.x*32, tid = threadIdx.x;
    __shared__ float sm[34][128];
    __shared__ float mx[32][128];
    __shared__ float wb[32][33], wm[32][33];
    int f = tid & 31, grp = tid >> 5, q0 = grp*4;
    float ab[4] = {0,0,0,0}, am[4] = {0,0,0,0};
    for (int half = 0; half < 2; half++){
        __syncthreads();
        for (int i = tid; i < 34*128; i += 256){
            int p = i >> 7, dd = i & 127;
            int n = tile0 + p - 1;
            sm[p][dd] = (n >= 0 && n < N)
                      ? g_xn2[((size_t)b*N + n)*EMB + half*128 + dd] : -1e30f;
        }
        __syncthreads();
        for (int i = tid; i < 32*128; i += 256){
            int p = i >> 7, dd = i & 127;
            mx[p][dd] = fmaxf(fmaxf(sm[p][dd], sm[p+1][dd]), sm[p+2][dd]);
        }
        for (int ch = 0; ch < 4; ch++){
            __syncthreads();
            for (int i = tid; i < 1024; i += 256){
                int ff = i >> 5, dd = i & 31;
                wb[ff][dd] = bw[ff*EMB + half*128 + ch*32 + dd];
                wm[ff][dd] = mw[ff*EMB + half*128 + ch*32 + dd];
            }
            __syncthreads();
            int dbase = ch*32;
            #pragma unroll 4
            for (int dd = 0; dd < 32; dd++){
                int d = dbase + dd;
                float w_b = wb[f][dd], w_m = wm[f][dd];
                ab[0] += sm[q0+1][d]*w_b; ab[1] += sm[q0+2][d]*w_b;
                ab[2] += sm[q0+3][d]*w_b; ab[3] += sm[q0+4][d]*w_b;
                am[0] += mx[q0+0][d]*w_m; am[1] += mx[q0+1][d]*w_m;
                am[2] += mx[q0+2][d]*w_m; am[3] += mx[q0+3][d]*w_m;
            }
        }
    }
    float bsc = rsqrtf(1.0f + 1e-5f);
    float sc = bng[96+f]*bsc, bi = bnb[96+f];
    #pragma unroll
    for (int tt = 0; tt < 4; tt++){
        int n = tile0 + q0 + tt;
        if (n < N){
            g_xbT[((size_t)b*32 + f)*1024 + n] = ab[tt];
            g_act[((size_t)b*N + n)*128 + 96 + f] = geluf(am[tt]*sc + bi);
        }
    }
}

// ---- inception convs: 128-pos tiles, 512 threads, 2-channel weight stage --
__global__ void __launch_bounds__(512) k_convs(const float* __restrict__ w39,
                        const float* __restrict__ w19, const float* __restrict__ w9,
                        const float* __restrict__ bng, const float* __restrict__ bnb,
                        int N){
    int b = blockIdx.y, tile0 = blockIdx.x*128, tid = threadIdx.x;
    __shared__ float sm[32][166];
    __shared__ float ws[2][32][69];
    for (int i = tid; i < 32*166; i += 512){
        int g = i/166, p = i - g*166;
        int n = tile0 + p - 19;
        sm[g][p] = (n >= 0 && n < N) ? g_xbT[((size_t)b*32 + g)*1024 + n] : 0.f;
    }
    int f = tid & 31, grp = tid >> 5;
    int pos0 = grp*8;
    float a39[8], a19[8], a9[8];
    #pragma unroll
    for (int j = 0; j < 8; j++){ a39[j]=0.f; a19[j]=0.f; a9[j]=0.f; }
    for (int gg = 0; gg < 16; gg++){
        int g0 = gg*2;
        __syncthreads();
        for (int i = tid; i < 2*32*67; i += 512){
            int gi = i/(32*67), rem = i - gi*(32*67);
            int ff = rem/67, j = rem - ff*67;
            int g = g0 + gi;
            float wv = (j < 39) ? w39[ff*1248 + g*39 + j]
                     : (j < 58) ? w19[ff*608 + g*19 + (j-39)]
                                : w9[ff*288 + g*9 + (j-58)];
            ws[gi][ff][j] = wv;
        }
        __syncthreads();
        #pragma unroll
        for (int gi = 0; gi < 2; gi++){
            int g = g0 + gi;
            {
                float xw[7];
                #pragma unroll
                for (int j = 0; j < 7; j++) xw[j] = sm[g][pos0 + j];
                #pragma unroll
                for (int k = 0; k < 39; k++){
                    float xn_ = sm[g][pos0 + k + 7];
                    float w = ws[gi][f][k];
                    a39[0]+=xw[0]*w; a39[1]+=xw[1]*w; a39[2]+=xw[2]*w; a39[3]+=xw[3]*w;
                    a39[4]+=xw[4]*w; a39[5]+=xw[5]*w; a39[6]+=xw[6]*w; a39[7]+=xn_*w;
                    #pragma unroll
                    for (int j = 0; j < 6; j++) xw[j] = xw[j+1];
                    xw[6] = xn_;
                }
            }
            {
                float xw[7];
                #pragma unroll
                for (int j = 0; j < 7; j++) xw[j] = sm[g][pos0 + 10 + j];
                #pragma unroll
                for (int k = 0; k < 19; k++){
                    float xn_ = sm[g][pos0 + 10 + k + 7];
                    float w = ws[gi][f][39 + k];
                    a19[0]+=xw[0]*w; a19[1]+=xw[1]*w; a19[2]+=xw[2]*w; a19[3]+=xw[3]*w;
                    a19[4]+=xw[4]*w; a19[5]+=xw[5]*w; a19[6]+=xw[6]*w; a19[7]+=xn_*w;
                    #pragma unroll
                    for (int j = 0; j < 6; j++) xw[j] = xw[j+1];
                    xw[6] = xn_;
                }
            }
            {
                float xw[7];
                #pragma unroll
                for (int j = 0; j < 7; j++) xw[j] = sm[g][pos0 + 15 + j];
                #pragma unroll
                for (int k = 0; k < 9; k++){
                    float xn_ = sm[g][pos0 + 15 + k + 7];
                    float w = ws[gi][f][58 + k];
                    a9[0]+=xw[0]*w; a9[1]+=xw[1]*w; a9[2]+=xw[2]*w; a9[3]+=xw[3]*w;
                    a9[4]+=xw[4]*w; a9[5]+=xw[5]*w; a9[6]+=xw[6]*w; a9[7]+=xn_*w;
                    #pragma unroll
                    for (int j = 0; j < 6; j++) xw[j] = xw[j+1];
                    xw[6] = xn_;
                }
            }
        }
    }
    float bsc = rsqrtf(1.0f + 1e-5f);
    float sc0 = bng[f]*bsc,    bi0 = bnb[f];
    float sc1 = bng[32+f]*bsc, bi1 = bnb[32+f];
    float sc2 = bng[64+f]*bsc, bi2 = bnb[64+f];
    #pragma unroll
    for (int tt = 0; tt < 8; tt++){
        int n = tile0 + pos0 + tt;
        if (n < N){
            size_t base = ((size_t)b*N + n)*128;
            g_act[base + f]      = geluf(a39[tt]*sc0 + bi0);
            g_act[base + 32 + f] = geluf(a19[tt]*sc1 + bi1);
            g_act[base + 64 + f] = geluf(a9[tt]*sc2 + bi2);
        }
    }
}

// ---- projection (64-token tiles): h (+)= act@W + b ; optional gelu --------
template<bool GACT>
__global__ void __launch_bounds__(256) k_proj(const float* __restrict__ W,
                        const float* __restrict__ bias, int T){
    int base = blockIdx.x*64, tid = threadIdx.x;
    int og = tid & 63, tg = tid >> 6;
    __shared__ __align__(16) float X[64*128];
    for (int i = tid; i < 64*128; i += 256){
        int tt = i >> 7, kk = i & 127;
        int t = base + tt;
        X[i] = (t < T) ? g_act[(size_t)t*128 + kk] : 0.f;
    }
    __syncthreads();
    float acc[16][4];
    gemm16x4<32>(W, X, og, tg, acc);
    float4 bv = ((const float4*)bias)[og];
    #pragma unroll
    for (int tt = 0; tt < 16; tt++){
        int t = base + tg*16 + tt;
        if (t < T){
            float4 hv = ((float4*)g_h)[(size_t)t*64 + og];
            hv.x += acc[tt][0] + bv.x;
            hv.y += acc[tt][1] + bv.y;
            hv.z += acc[tt][2] + bv.z;
            hv.w += acc[tt][3] + bv.w;
            if (GACT){
                hv.x = geluf(hv.x); hv.y = geluf(hv.y);
                hv.z = geluf(hv.z); hv.w = geluf(hv.w);
            }
            ((float4*)g_h)[(size_t)t*64 + og] = hv;
        }
    }
}

// ---- final head fused with end-score attn; partials then combine ----------
__global__ void k_final_part(const float* __restrict__ hw, const float* __restrict__ hb,
                             const float* __restrict__ b1, const float* __restrict__ w2,
                             const float* __restrict__ b2){
    int b = blockIdx.x, c = blockIdx.y;
    int tid = threadIdx.x, w = tid >> 5, l = tid & 31;
    __shared__ float s_hw[EMB];
    __shared__ float wacc[8];
    s_hw[tid] = hw[tid];
    __syncthreads();
    int j0 = c*65, j1 = min(j0 + 65, N1);
    float local = 0.f, hbias = hb[0];
    for (int j = j0 + w; j < j1; j += 8){
        size_t t = (size_t)b*N1 + j;
        float v[8];
        #pragma unroll
        for (int q = 0; q < 8; q++) v[q] = g_h[t*EMB + l + 32*q];
        float hp[8];
        #pragma unroll
        for (int jj = 0; jj < 8; jj++){
            float a = 0.f;
            #pragma unroll
            for (int q = 0; q < 8; q++) a += v[q]*g_w1T[jj*EMB + l + 32*q];
            hp[jj] = a;
        }
        #pragma unroll
        for (int jj = 0; jj < 8; jj++) hp[jj] = wsum(hp[jj]);
        float s = 0.f;
        #pragma unroll
        for (int q = 0; q < 8; q++) s += geluf(v[q])*s_hw[l + 32*q];
        s = wsum(s);
        if (l == 0){
            float s2 = b2[0];
            #pragma unroll
            for (int jj = 0; jj < 8; jj++) s2 += tanhf(hp[jj] + b1[jj])*w2[jj];
            float esc = 1.0f/(1.0f + expf(-s2));
            local += (s + hbias)*esc;
        }
    }
    if (l == 0) wacc[w] = local;
    __syncthreads();
    if (tid == 0){
        float tot = 0.f;
        #pragma unroll
        for (int i = 0; i < 8; i++) tot += wacc[i];
        g_part[b*8 + c] = tot;
    }
}

__global__ void k_final_comb(float* __restrict__ out, int out_size){
    int b = threadIdx.x;
    if (b < BB){
        float s = 0.f;
        #pragma unroll
        for (int c = 0; c < 8; c++) s += g_part[b*8 + c];
        out[b] = s/(float)N1;
    }
    if (b == 0 && out_size > BB){
        float m = (g_imp[0]+g_imp[1]+g_imp[2]+g_imp[3])*0.25f;
        float v = 0.f;
        #pragma unroll
        for (int e = 0; e < 4; e++){ float dv = g_imp[e]-m; v += dv*dv; }
        v *= (1.0f/3.0f);
        out[BB] = v/(m*m + 1e-10f);
    }
}

// ---------------------------------------------------------------------------
extern "C" void kernel_launch(void* const* d_in, const int* in_sizes, int n_in,
                              void* d_out, int out_size){
    const float* x       = (const float*)d_in[0];
    const float* emb_w   = (const float*)d_in[3];
    const float* emb_b   = (const float*)d_in[4];
    const float* pos     = (const float*)d_in[5];
    const float* aw1     = (const float*)d_in[6];
    const float* ab1     = (const float*)d_in[7];
    const float* aw2     = (const float*)d_in[8];
    const float* ab2     = (const float*)d_in[9];
    const float* gw      = (const float*)d_in[10];
    const float* gb      = (const float*)d_in[11];
    const float* ew1     = (const float*)d_in[12];
    const float* eb1     = (const float*)d_in[13];
    const float* ew2     = (const float*)d_in[14];
    const float* eb2     = (const float*)d_in[15];
    const float* mgam    = (const float*)d_in[16];
    const float* n1g     = (const float*)d_in[17];
    const float* n2g     = (const float*)d_in[18];
    const float* bott    = (const float*)d_in[19];
    const float* w39     = (const float*)d_in[20];
    const float* w19     = (const float*)d_in[21];
    const float* w9      = (const float*)d_in[22];
    const float* mpw     = (const float*)d_in[23];
    const float* bng     = (const float*)d_in[24];
    const float* bnb     = (const float*)d_in[25];
    const float* pw      = (const float*)d_in[26];
    const float* pb      = (const float*)d_in[27];
    const float* hw      = (const float*)d_in[28];
    const float* hb      = (const float*)d_in[29];
    float* out = (float*)d_out;

    cudaFuncSetAttribute(k_expert2, cudaFuncAttributeMaxDynamicSharedMemorySize,
                         64*256*4);

    k_prep<<<136, 256>>>(emb_w, aw1);
    k_embed<<<dim3(16, BB), 256>>>(x, emb_b, pos);

    // ---- layer 0 (dense): fused norm1+attn+scale+norm2; incep; proj+gelu
    k_norm_attn<1><<<(BB*N0)/8, 256>>>(n1g, n2g, ab1, aw2, ab2, N0, BB*N0);
    k_bott<<<dim3(32, BB), 256>>>(bott, mpw, bng, bnb, N0);
    k_convs<<<dim3(8, BB), 512>>>(w39, w19, w9, bng, bnb, N0);
    k_proj<true><<<(BB*N0 + 63)/64, 256>>>(pw, pb, BB*N0);

    // ---- layer 1 (sparse, ratio 0.5)
    k_norm_attn<0><<<(BB*N0)/8, 256>>>(n1g + EMB, n2g, ab1, aw2, ab2, N0, BB*N0);
    k_topk<<<BB, 512>>>();
    k_gather<<<(BB*K1)/8, 256>>>(n2g + EMB);
    k_extra_part<<<dim3(BB, 8), 256>>>();
    k_extra_comb<<<BB, 256>>>(n2g + EMB);
    // MoE
    k_zero<<<1, 32>>>();
    k_gate<<<(T1 + 7)/8, 256>>>(gw, gb);
    k_imp<<<4, 256>>>();
    k_expert2<<<dim3((T1 + 63)/64, 4), 256, 64*256*4>>>(ew1, eb1, ew2, eb2);
    k_moe_combine<<<(T1 + 7)/8, 256>>>(mgam);
    // Inception branch (layer-1 weights)
    k_bott<<<dim3(17, BB), 256>>>(bott + 32*EMB, mpw + 32*EMB,
                                  bng + 128, bnb + 128, N1);
    k_convs<<<dim3(5, BB), 512>>>(w39 + 32*32*39, w19 + 32*32*19,
                                  w9 + 32*32*9, bng + 128, bnb + 128, N1);
    k_proj<false><<<(T1 + 63)/64, 256>>>(pw + 128*EMB, pb + EMB, T1);
    // fused end-scores + gelu + head + weighted mean
    k_final_part<<<dim3(BB, 8), 256>>>(hw, hb, ab1, aw2, ab2);
    k_final_comb<<<1, 64>>>(out, out_size);
}